// round 16
// baseline (speedup 1.0000x reference)
#include <cuda_runtime.h>
#include <cuda_bf16.h>

// Scales: S={56,28,14,7}, C={64,128,256,512}, HW={3136,784,196,49}
// HWC scratch offsets (floats): 0, 200704, 301056, 351232; total 376320 floats.
#define HWC_TOTAL 376320
#define NPTS_MAX  131072
#define PTS_PER_BLK 16

__device__ __align__(16) float g_hwc[HWC_TOTAL];

// Pre-pass: transpose batch-b CHW slices -> HWC scratch (write-coalesced).
__global__ void prep_kernel(const float* __restrict__ f0, const float* __restrict__ f1,
                            const float* __restrict__ f2, const float* __restrict__ f3,
                            const int* __restrict__ bptr)
{
    int tid = blockIdx.x * blockDim.x + threadIdx.x;
    if (tid >= HWC_TOTAL) return;
    int b = bptr ? *bptr : 3;
    const float* src; int e, clog2, HW;
    if (tid < 200704)      { src = f0; e = tid;          clog2 = 6; HW = 3136; }
    else if (tid < 301056) { src = f1; e = tid - 200704; clog2 = 7; HW = 784;  }
    else if (tid < 351232) { src = f2; e = tid - 301056; clog2 = 8; HW = 196;  }
    else                   { src = f3; e = tid - 351232; clog2 = 9; HW = 49;   }
    int C = 1 << clog2;
    int c = e & (C - 1);       // channel (fastest in dst)
    int p = e >> clog2;        // pixel index
    g_hwc[tid] = __ldg(&src[(size_t)b * C * HW + (size_t)c * HW + p]);
}

// Main kernel: each 256-thread block owns PTS_PER_BLK consecutive points.
// Threads 0..15 compute the per-scale gather offsets (or -1) for one point
// each, directly from pts, into smem — no separate point pre-pass, no global
// offset array. Threads 0..239 then each own a fixed float4 chunk of the
// 960-float row; the point loop is unrolled x4 so each thread keeps 4
// independent L2-hit gathers in flight before 4 coalesced streaming stores
// (warp store instruction = 512B contiguous, all sectors full).
// chunk [0,16): scale0; [16,48): scale1; [48,112): scale2; [112,240): scale3.
__global__ void __launch_bounds__(256) gather_kernel(const float* __restrict__ pts,
                                                     float4* __restrict__ out, int N)
{
    __shared__ int4 s_off[PTS_PER_BLK];
    int tid = threadIdx.x;
    int p0 = blockIdx.x * PTS_PER_BLK;

    if (tid < PTS_PER_BLK) {
        int n = p0 + tid;
        if (n < N) {
            float q0 = __ldg(&pts[3 * n + 0]);
            float q1 = __ldg(&pts[3 * n + 1]);
            float q2 = __ldg(&pts[3 * n + 2]);
            float h = 248.0f * (q1 / q2) + 111.5f;
            float w = 248.0f * (q0 / (-q2)) + 111.5f;
            h = fminf(fmaxf(h, 0.0f), 223.0f);
            w = fminf(fmaxf(w, 0.0f), 223.0f);

            const int   S[4]    = {56, 28, 14, 7};
            const int   C[4]    = {64, 128, 256, 512};
            const int   base[4] = {0, 200704, 301056, 351232};
            const float inv[4]  = {0.25f, 0.125f, 0.0625f, 0.03125f};

            int4 r;
            int* rp = (int*)&r;
            #pragma unroll
            for (int s = 0; s < 4; s++) {
                float x = h * inv[s];   // == h / (224/S): divisor is an exact power of two
                float y = w * inv[s];
                int x1 = (int)floorf(x);
                int y1 = (int)floorf(y);
                int x2 = min((int)ceilf(x), S[s] - 1);
                int y2 = min((int)ceilf(y), S[s] - 1);
                // reference truncates before weighting, so only w11=(x2-x1)*(y2-y1) in {0,1} survives
                int wgt = (x2 - x1) * (y2 - y1);
                rp[s] = wgt ? (base[s] + (x1 * S[s] + y1) * C[s]) : -1;
            }
            s_off[tid] = r;
        }
    }
    __syncthreads();

    if (tid >= 240) return;

    // Loop-invariant: which component of off4 this thread uses, and its chunk.
    int comp, c4;
    if (tid < 16)       { comp = 0; c4 = tid;       }
    else if (tid < 48)  { comp = 1; c4 = tid - 16;  }
    else if (tid < 112) { comp = 2; c4 = tid - 48;  }
    else                { comp = 3; c4 = tid - 112; }
    int c16 = c4 * 4;

    const float4 zero = make_float4(0.f, 0.f, 0.f, 0.f);

    if (p0 + PTS_PER_BLK <= N) {
        // Fast path: no bounds checks, 4 independent loads in flight per batch.
        #pragma unroll 1
        for (int kb = 0; kb < PTS_PER_BLK; kb += 4) {
            float4 v[4];
            #pragma unroll
            for (int j = 0; j < 4; j++) {
                int4 o4 = s_off[kb + j];
                int off = (comp == 0) ? o4.x : (comp == 1) ? o4.y
                        : (comp == 2) ? o4.z : o4.w;
                v[j] = zero;
                if (off >= 0)
                    v[j] = __ldg((const float4*)&g_hwc[off + c16]);
            }
            float4* dst = out + (size_t)(p0 + kb) * 240 + tid;
            #pragma unroll
            for (int j = 0; j < 4; j++)
                __stcs(dst + (size_t)j * 240, v[j]);
        }
    } else {
        // Tail block: per-point bounds checks.
        for (int k = 0; k < PTS_PER_BLK; k++) {
            int p = p0 + k;
            if (p >= N) break;
            int4 o4 = s_off[k];
            int off = (comp == 0) ? o4.x : (comp == 1) ? o4.y
                    : (comp == 2) ? o4.z : o4.w;
            float4 v = zero;
            if (off >= 0)
                v = __ldg((const float4*)&g_hwc[off + c16]);
            __stcs(&out[(size_t)p * 240 + tid], v);
        }
    }
}

extern "C" void kernel_launch(void* const* d_in, const int* in_sizes, int n_in,
                              void* d_out, int out_size)
{
    const float* f0  = (const float*)d_in[0];
    const float* f1  = (const float*)d_in[1];
    const float* f2  = (const float*)d_in[2];
    const float* f3  = (const float*)d_in[3];
    const float* pts = (const float*)d_in[4];
    const int*   bp  = (n_in >= 6) ? (const int*)d_in[5] : nullptr;

    int N = in_sizes[4] / 3;
    if (N > NPTS_MAX) N = NPTS_MAX;

    {
        int threads = 256;
        int blocks = (HWC_TOTAL + threads - 1) / threads;
        prep_kernel<<<blocks, threads>>>(f0, f1, f2, f3, bp);
    }
    {
        int blocks = (N + PTS_PER_BLK - 1) / PTS_PER_BLK;
        gather_kernel<<<blocks, 256>>>(pts, (float4*)d_out, N);
    }
}